// round 1
// baseline (speedup 1.0000x reference)
#include <cuda_runtime.h>

#define B_      16
#define L_      65536
#define H_      64
#define K_      64
#define WARMUP  63
#define LOUT    (L_ - WARMUP)     /* 65473 */
#define TILE_T  256
#define TPB     256
#define XS_LEN  (TILE_T + 72)     /* 328: covers t0l+h+8 max = 319 */

__global__ __launch_bounds__(TPB, 2)
void hankel_fb_kernel(const float* __restrict__ x,
                      const float* __restrict__ W,
                      const float* __restrict__ bias,
                      float* __restrict__ out)
{
    __shared__ float xs[XS_LEN];
    __shared__ float Wt[H_][K_];   // Wt[h][k] (transposed for broadcast float4 loads)
    __shared__ float Sk[K_];       // per-filter sum of weights

    const int tile   = blockIdx.x;
    const int b      = blockIdx.y;
    const int tid    = threadIdx.x;
    const int t_base = tile * TILE_T;

    // ---- load x tile (guarded; tail beyond L_ unused but zero-filled) ----
    const float* __restrict__ xb = x + (size_t)b * L_;
    for (int i = tid; i < XS_LEN; i += TPB) {
        int g = t_base + i;
        xs[i] = (g < L_) ? xb[g] : 0.0f;
    }
    // ---- load W transposed ----
    for (int i = tid; i < K_ * H_; i += TPB) {
        int k = i >> 6, h = i & 63;
        Wt[h][k] = W[i];
    }
    __syncthreads();

    if (tid < K_) {
        float s = 0.0f;
        #pragma unroll
        for (int h = 0; h < H_; ++h) s += Wt[h][tid];
        Sk[tid] = s;
    }
    __syncthreads();

    const int lane = tid & 31;
    const int warp = tid >> 5;
    const int k0   = warp * 8;     // warp owns 8 filters
    const int t0l  = lane * 8;     // lane owns 8 consecutive positions

    float acc[8][8];
    #pragma unroll
    for (int i = 0; i < 8; ++i)
        #pragma unroll
        for (int j = 0; j < 8; ++j) acc[i][j] = 0.0f;

    // rolling x window: slot (h+i)&7 holds x[t0l + h + i]
    float xr[8];
    #pragma unroll
    for (int i = 0; i < 8; ++i) xr[i] = xs[t0l + i];

    // ---- main loop: 64 h-steps, 64 FMA each; unroll-8 keeps ring indices constant ----
    #pragma unroll 1
    for (int hb = 0; hb < 8; ++hb) {
        #pragma unroll
        for (int u = 0; u < 8; ++u) {
            const int h = hb * 8 + u;
            float4 w0 = *(const float4*)&Wt[h][k0];       // broadcast within warp
            float4 w1 = *(const float4*)&Wt[h][k0 + 4];
            float wv[8] = {w0.x, w0.y, w0.z, w0.w, w1.x, w1.y, w1.z, w1.w};
            #pragma unroll
            for (int i = 0; i < 8; ++i) {
                const float xv = xr[(u + i) & 7];
                #pragma unroll
                for (int j = 0; j < 8; ++j)
                    acc[i][j] = fmaf(xv, wv[j], acc[i][j]);
            }
            xr[u & 7] = xs[t0l + h + 8];                  // reload freed slot
        }
    }

    // ---- epilogue: sliding-window stats + affine + bias + relu ----
    float sum = 0.0f, sq = 0.0f;
    #pragma unroll
    for (int h = 0; h < H_; ++h) {
        float v = xs[t0l + h];
        sum += v; sq += v * v;
    }

    float bk[8], sk[8];
    #pragma unroll
    for (int j = 0; j < 8; ++j) { bk[j] = bias[k0 + j]; sk[j] = Sk[k0 + j]; }

    float* __restrict__ outb = out + (size_t)b * LOUT * K_;
    #pragma unroll
    for (int i = 0; i < 8; ++i) {
        if (i) {  // roll window by one
            float vo = xs[t0l + i - 1];
            float vn = xs[t0l + i - 1 + H_];
            sum += vn - vo;
            sq  += vn * vn - vo * vo;
        }
        const int t = t_base + t0l + i;
        if (t < LOUT) {
            float mu  = sum * (1.0f / 64.0f);
            float var = (sq - sum * mu) * (1.0f / 63.0f);   // ddof=1
            var = fmaxf(var, 0.0f);
            float inv = 1.0f / (sqrtf(var) + 1e-6f);        // eps added to sd
            float res[8];
            #pragma unroll
            for (int j = 0; j < 8; ++j) {
                float v = (acc[i][j] - mu * sk[j]) * inv + bk[j];
                res[j] = fmaxf(v, 0.0f);
            }
            float* o = outb + (size_t)t * K_ + k0;
            *(float4*)o       = make_float4(res[0], res[1], res[2], res[3]);
            *(float4*)(o + 4) = make_float4(res[4], res[5], res[6], res[7]);
        }
    }
}

__global__ void fill_tail_kernel(float* p, int n, float v) {
    int i = blockIdx.x * blockDim.x + threadIdx.x;
    if (i < n) p[i] = v;
}

extern "C" void kernel_launch(void* const* d_in, const int* in_sizes, int n_in,
                              void* d_out, int out_size)
{
    const float* x  = (const float*)d_in[0];
    const float* W  = (const float*)d_in[1];
    const float* bb = (const float*)d_in[2];
    float* out = (float*)d_out;

    dim3 grid((LOUT + TILE_T - 1) / TILE_T, B_);
    hankel_fb_kernel<<<grid, TPB>>>(x, W, bb, out);

    // If the harness flattened the (array, warmup) tuple, the tail holds warmup=63.
    long long n_main = (long long)B_ * LOUT * K_;
    if ((long long)out_size > n_main) {
        int extra = (int)((long long)out_size - n_main);
        fill_tail_kernel<<<(extra + 63) / 64, 64>>>(out + n_main, extra, 63.0f);
    }
}

// round 2
// speedup vs baseline: 1.1874x; 1.1874x over previous
#include <cuda_runtime.h>

#define B_      16
#define L_      65536
#define H_      64
#define K_      64
#define WARMUP  63
#define LOUT    (L_ - WARMUP)     /* 65473 */
#define TILE_T  256
#define TPB     256
#define XS_LEN  (TILE_T + 72)     /* covers t0l + h + 8 max = 319 */

typedef unsigned long long u64;

__device__ __forceinline__ u64 pack2(float lo, float hi) {
    u64 r; asm("mov.b64 %0, {%1, %2};" : "=l"(r) : "f"(lo), "f"(hi)); return r;
}
__device__ __forceinline__ void unpack2(u64 v, float& lo, float& hi) {
    asm("mov.b64 {%0, %1}, %2;" : "=f"(lo), "=f"(hi) : "l"(v));
}
// d = a*b + d  (packed 2x fp32, Blackwell FFMA2)
__device__ __forceinline__ void ffma2(u64& d, u64 a, u64 b) {
    asm("fma.rn.f32x2 %0, %1, %2, %3;" : "=l"(d) : "l"(a), "l"(b), "l"(d));
}

__global__ __launch_bounds__(TPB, 2)
void hankel_fb_kernel(const float* __restrict__ x,
                      const float* __restrict__ W,
                      const float* __restrict__ bias,
                      float* __restrict__ out)
{
    __shared__ float xs[XS_LEN];
    __shared__ float Wt[H_][K_];   // Wt[h][k] (transposed: broadcast float4 loads per warp)
    __shared__ float Sk[K_];       // per-filter weight sums

    const int tile   = blockIdx.x;
    const int b      = blockIdx.y;
    const int tid    = threadIdx.x;
    const int t_base = tile * TILE_T;

    const float* __restrict__ xb = x + (size_t)b * L_;
    for (int i = tid; i < XS_LEN; i += TPB) {
        int g = t_base + i;
        xs[i] = (g < L_) ? xb[g] : 0.0f;
    }
    for (int i = tid; i < K_ * H_; i += TPB) {
        int k = i >> 6, h = i & 63;
        Wt[h][k] = W[i];
    }
    __syncthreads();

    if (tid < K_) {
        float s = 0.0f;
        #pragma unroll
        for (int h = 0; h < H_; ++h) s += Wt[h][tid];
        Sk[tid] = s;
    }
    __syncthreads();

    const int lane = tid & 31;
    const int warp = tid >> 5;
    const int k0   = warp * 8;     // warp owns 8 filters (4 packed pairs)
    const int t0l  = lane * 8;     // lane owns 8 consecutive positions

    // packed accumulators: acc2[i][j] = {out[t0l+i][k0+2j], out[t0l+i][k0+2j+1]}
    u64 acc2[8][4];
    #pragma unroll
    for (int i = 0; i < 8; ++i)
        #pragma unroll
        for (int j = 0; j < 4; ++j) acc2[i][j] = 0ULL;

    // rolling x window, duplicated into both halves: slot (h+i)&7 holds {x,x}[t0l+h+i]
    u64 xd[8];
    #pragma unroll
    for (int i = 0; i < 8; ++i) { float v = xs[t0l + i]; xd[i] = pack2(v, v); }

    // ---- main loop: 64 h-steps x 32 FFMA2 each (ring indices compile-time via unroll-8) ----
    #pragma unroll 1
    for (int hb = 0; hb < 8; ++hb) {
        #pragma unroll
        for (int u = 0; u < 8; ++u) {
            const int h = hb * 8 + u;
            float4 w0 = *(const float4*)&Wt[h][k0];       // warp-broadcast, conflict-free
            float4 w1 = *(const float4*)&Wt[h][k0 + 4];
            u64 wp[4];
            wp[0] = pack2(w0.x, w0.y);
            wp[1] = pack2(w0.z, w0.w);
            wp[2] = pack2(w1.x, w1.y);
            wp[3] = pack2(w1.z, w1.w);
            #pragma unroll
            for (int i = 0; i < 8; ++i) {
                const u64 xv = xd[(u + i) & 7];
                #pragma unroll
                for (int j = 0; j < 4; ++j)
                    ffma2(acc2[i][j], xv, wp[j]);
            }
            float v = xs[t0l + h + 8];                    // refill freed ring slot
            xd[u & 7] = pack2(v, v);
        }
    }

    // ---- epilogue: sliding-window stats + affine + bias + relu ----
    float sum = 0.0f, sq = 0.0f;
    #pragma unroll
    for (int h = 0; h < H_; ++h) {
        float v = xs[t0l + h];
        sum += v; sq += v * v;
    }

    float bk[8], sk[8];
    #pragma unroll
    for (int j = 0; j < 8; ++j) { bk[j] = bias[k0 + j]; sk[j] = Sk[k0 + j]; }

    float* __restrict__ outb = out + (size_t)b * LOUT * K_;
    #pragma unroll
    for (int i = 0; i < 8; ++i) {
        if (i) {
            float vo = xs[t0l + i - 1];
            float vn = xs[t0l + i - 1 + H_];
            sum += vn - vo;
            sq  += vn * vn - vo * vo;
        }
        const int t = t_base + t0l + i;
        if (t < LOUT) {
            float mu  = sum * (1.0f / 64.0f);
            float var = (sq - sum * mu) * (1.0f / 63.0f);   // ddof=1
            var = fmaxf(var, 0.0f);
            float inv = 1.0f / (sqrtf(var) + 1e-6f);        // eps added to sd
            float res[8];
            #pragma unroll
            for (int j = 0; j < 4; ++j) {
                float a0, a1; unpack2(acc2[i][j], a0, a1);
                res[2*j]   = fmaxf((a0 - mu * sk[2*j])   * inv + bk[2*j],   0.0f);
                res[2*j+1] = fmaxf((a1 - mu * sk[2*j+1]) * inv + bk[2*j+1], 0.0f);
            }
            float* o = outb + (size_t)t * K_ + k0;
            *(float4*)o       = make_float4(res[0], res[1], res[2], res[3]);
            *(float4*)(o + 4) = make_float4(res[4], res[5], res[6], res[7]);
        }
    }
}

__global__ void fill_tail_kernel(float* p, int n, float v) {
    int i = blockIdx.x * blockDim.x + threadIdx.x;
    if (i < n) p[i] = v;
}

extern "C" void kernel_launch(void* const* d_in, const int* in_sizes, int n_in,
                              void* d_out, int out_size)
{
    const float* x  = (const float*)d_in[0];
    const float* W  = (const float*)d_in[1];
    const float* bb = (const float*)d_in[2];
    float* out = (float*)d_out;

    dim3 grid((LOUT + TILE_T - 1) / TILE_T, B_);
    hankel_fb_kernel<<<grid, TPB>>>(x, W, bb, out);

    long long n_main = (long long)B_ * LOUT * K_;
    if ((long long)out_size > n_main) {
        int extra = (int)((long long)out_size - n_main);
        fill_tail_kernel<<<(extra + 63) / 64, 64>>>(out + n_main, extra, 63.0f);
    }
}